// round 12
// baseline (speedup 1.0000x reference)
#include <cuda_runtime.h>
#include <math.h>

#define NLOC 196
#define PI_F 3.14159265358979323846f

// spread bits of 4-bit x: bit i -> bit 2i
__device__ __forceinline__ int spread4(int x) {
    return (x & 1) | ((x & 2) << 1) | ((x & 4) << 2) | ((x & 8) << 3);
}

// One wire contraction of the pair-tensor: last base-4 digit (pair p=2k+k')
// -> base-3 digit m over (1, C, S) basis:
//   m=0: 0.5*(x00+x11)   m=1: 0.5*(x00-x11)   m=2: 0.5*(x01+x10)
#define CSTEP(IN, OUT, NB, NM)                                         \
  do {                                                                 \
    const int cnt = (NB) * 3 * (NM);                                   \
    for (int e = tid; e < 4 * cnt; e += 256) {                         \
      int i = e / cnt; int o = e - i * cnt;                            \
      int M = o % (NM); int rest = o / (NM);                           \
      int m = rest % 3; int B = rest / 3;                              \
      float x0 = IN[i][(B * 4 + 0) * (NM) + M];                        \
      float x1 = IN[i][(B * 4 + 1) * (NM) + M];                        \
      float x2 = IN[i][(B * 4 + 2) * (NM) + M];                        \
      float x3 = IN[i][(B * 4 + 3) * (NM) + M];                        \
      float rV;                                                        \
      if (m == 0)      rV = 0.5f * (x0 + x3);                          \
      else if (m == 1) rV = 0.5f * (x0 - x3);                          \
      else             rV = 0.5f * (x1 + x2);                          \
      OUT[i][o] = rV;                                                  \
    }                                                                  \
    __syncthreads();                                                   \
  } while (0)

// ---------------------------------------------------------------------------
// One block per patch location (196 blocks, 256 threads).
// Precompute (all threads, divergence-free):
//   U (16x16 complex, post-input-layer circuit) via shuffle butterflies,
//   A_i[k,k'] = sum_K d_i(K)(P P + Q Q),   then wire-by-wire contraction to
//   W (4 x 81):  z = W (1,C0,S0)x(1,C1,S1)x(1,C2,S2)x(1,C3,S3), FULL angles.
// Phase 3: each thread evaluates 2 samples: 4 __sincosf + 81*(LDS.128 + 8 FMA).
// Wire j <-> bit (3-j) of state index K.
// ---------------------------------------------------------------------------
__global__ void __launch_bounds__(256, 2) qf_fused(const float* __restrict__ x,
                                                   const float* __restrict__ params,
                                                   float* __restrict__ out) {
    __shared__ float  sP[16 * 17], sQ[16 * 17];   // U re/im, [K*17 + col] (pad: no STS conflicts)
    __shared__ float  bufA[4][256], bufB[4][256]; // contraction ping-pong
    __shared__ float4 sW[81];                     // W interleaved (z0,z1,z2,z3)
    __shared__ float  sPart[2][8];                // per-warp (sum, sumsq)

    const int p = blockIdx.x;
    const int r = p / 14, c = p - r * 14;
    const int base = (2 * r) * 28 + 2 * c;
    const int tid = threadIdx.x;

    // ---- Phase 1: load 2 samples per thread + stats partials ----
    const float* xb0 = x + tid * 784 + base;
    const float* xb1 = x + (tid + 256) * 784 + base;
    float2 a0 = *reinterpret_cast<const float2*>(xb0);
    float2 a1 = *reinterpret_cast<const float2*>(xb0 + 28);
    float2 b0 = *reinterpret_cast<const float2*>(xb1);
    float2 b1 = *reinterpret_cast<const float2*>(xb1 + 28);

    float sum = (a0.x + a0.y) + (a1.x + a1.y) + (b0.x + b0.y) + (b1.x + b1.y);
    float sq  = a0.x * a0.x + a0.y * a0.y + a1.x * a1.x + a1.y * a1.y
              + b0.x * b0.x + b0.y * b0.y + b1.x * b1.x + b1.y * b1.y;
    #pragma unroll
    for (int o = 16; o > 0; o >>= 1) {
        sum += __shfl_down_sync(0xffffffffu, sum, o);
        sq  += __shfl_down_sync(0xffffffffu, sq,  o);
    }
    if ((tid & 31) == 0) { sPart[0][tid >> 5] = sum; sPart[1][tid >> 5] = sq; }

    // ---- Phase 2a: build U via shuffle butterflies; thread = (col, K) ----
    {
        const int col = tid >> 4, K = tid & 15;
        float vr = (K == col) ? 1.f : 0.f, vi = 0.f;
        #pragma unroll
        for (int l = 0; l < 2; l++) {
            // RY(params[l][w][0])
            #pragma unroll
            for (int wi = 0; wi < 4; wi++) {
                float ss, cc; __sincosf(0.5f * params[(l * 4 + wi) * 3 + 0], &ss, &cc);
                int m = 8 >> wi;
                float orr = __shfl_xor_sync(0xffffffffu, vr, m);
                float oii = __shfl_xor_sync(0xffffffffu, vi, m);
                if (K & m) { vr = fmaf(ss, orr, cc * vr);  vi = fmaf(ss, oii, cc * vi); }
                else       { vr = fmaf(-ss, orr, cc * vr); vi = fmaf(-ss, oii, cc * vi); }
            }
            // CNOT(i -> i+1)
            #pragma unroll
            for (int i = 0; i < 3; i++) {
                int cm = 8 >> i, tm = 8 >> (i + 1);
                float orr = __shfl_xor_sync(0xffffffffu, vr, tm);
                float oii = __shfl_xor_sync(0xffffffffu, vi, tm);
                if (K & cm) { vr = orr; vi = oii; }
            }
            // RY(params[l][w][1])
            #pragma unroll
            for (int wi = 0; wi < 4; wi++) {
                float ss, cc; __sincosf(0.5f * params[(l * 4 + wi) * 3 + 1], &ss, &cc);
                int m = 8 >> wi;
                float orr = __shfl_xor_sync(0xffffffffu, vr, m);
                float oii = __shfl_xor_sync(0xffffffffu, vi, m);
                if (K & m) { vr = fmaf(ss, orr, cc * vr);  vi = fmaf(ss, oii, cc * vi); }
                else       { vr = fmaf(-ss, orr, cc * vr); vi = fmaf(-ss, oii, cc * vi); }
            }
            // CNOT(i+1 -> i)
            #pragma unroll
            for (int i = 0; i < 3; i++) {
                int cm = 8 >> (i + 1), tm = 8 >> i;
                float orr = __shfl_xor_sync(0xffffffffu, vr, tm);
                float oii = __shfl_xor_sync(0xffffffffu, vi, tm);
                if (K & cm) { vr = orr; vi = oii; }
            }
            // RZ(params[l][w][2]): |0> *= e^{-i th/2}, |1> *= e^{+i th/2}
            #pragma unroll
            for (int wi = 0; wi < 4; wi++) {
                float ss, cc; __sincosf(0.5f * params[(l * 4 + wi) * 3 + 2], &ss, &cc);
                int m = 8 >> wi;
                float rr = vr, ii = vi;
                if (K & m) { vr = rr * cc - ii * ss; vi = ii * cc + rr * ss; }
                else       { vr = rr * cc + ii * ss; vi = ii * cc - rr * ss; }
            }
        }
        sP[K * 17 + col] = vr;
        sQ[K * 17 + col] = vi;
    }
    __syncthreads();

    // ---- Phase 2b: A_i[k,k'] -> bufA at interleaved pair index ----
    {
        const int k = tid >> 4, kp = tid & 15;
        float A0 = 0.f, A1 = 0.f, A2 = 0.f, A3 = 0.f;
        #pragma unroll
        for (int K = 0; K < 16; K++) {
            float pp = fmaf(sP[K * 17 + k], sP[K * 17 + kp],
                            sQ[K * 17 + k] * sQ[K * 17 + kp]);
            if (K & 8) A0 -= pp; else A0 += pp;
            if (K & 4) A1 -= pp; else A1 += pp;
            if (K & 2) A2 -= pp; else A2 += pp;
            if (K & 1) A3 -= pp; else A3 += pp;
        }
        int pi = 2 * spread4(k) + spread4(kp);   // base-4 digits p_j = 2 k_j + k'_j
        bufA[0][pi] = A0; bufA[1][pi] = A1; bufA[2][pi] = A2; bufA[3][pi] = A3;
    }
    __syncthreads();

    // ---- Phase 2c: contract 4 wires: 256 -> 192 -> 144 -> 108 -> 81 ----
    CSTEP(bufA, bufB, 64, 1);
    CSTEP(bufB, bufA, 16, 3);
    CSTEP(bufA, bufB, 4, 9);
    CSTEP(bufB, bufA, 1, 27);

    if (tid < 81)
        sW[tid] = make_float4(bufA[0][tid], bufA[1][tid], bufA[2][tid], bufA[3][tid]);
    __syncthreads();

    // ---- Stats finalize (redundant per-thread, no extra barrier) ----
    float S = 0.f, Q = 0.f;
    #pragma unroll
    for (int i = 0; i < 8; i++) { S += sPart[0][i]; Q += sPart[1][i]; }
    const float mean  = S * (1.f / 2048.f);
    const float ssd   = Q - S * S * (1.f / 2048.f);
    const float sd    = sqrtf(ssd * (1.f / 2047.f));
    const float scale = __fdividef(PI_F, sd + 1e-8f);

    // ---- Phase 3: z = W * ((1,C0,S0) x (1,C1,S1) x (1,C2,S2) x (1,C3,S3)) ----
    // FULL angles (no /2): pair products absorbed into W.
    float v01a[9], v23a[9], v01b[9], v23b[9];
    {
        float C0, S0, C1, S1, C2, S2, C3, S3;
        __sincosf((a0.x - mean) * scale, &S0, &C0);
        __sincosf((a0.y - mean) * scale, &S1, &C1);
        __sincosf((a1.x - mean) * scale, &S2, &C2);
        __sincosf((a1.y - mean) * scale, &S3, &C3);
        v01a[0] = 1.f; v01a[1] = C1;      v01a[2] = S1;
        v01a[3] = C0;  v01a[4] = C0 * C1; v01a[5] = C0 * S1;
        v01a[6] = S0;  v01a[7] = S0 * C1; v01a[8] = S0 * S1;
        v23a[0] = 1.f; v23a[1] = C3;      v23a[2] = S3;
        v23a[3] = C2;  v23a[4] = C2 * C3; v23a[5] = C2 * S3;
        v23a[6] = S2;  v23a[7] = S2 * C3; v23a[8] = S2 * S3;
    }
    {
        float C0, S0, C1, S1, C2, S2, C3, S3;
        __sincosf((b0.x - mean) * scale, &S0, &C0);
        __sincosf((b0.y - mean) * scale, &S1, &C1);
        __sincosf((b1.x - mean) * scale, &S2, &C2);
        __sincosf((b1.y - mean) * scale, &S3, &C3);
        v01b[0] = 1.f; v01b[1] = C1;      v01b[2] = S1;
        v01b[3] = C0;  v01b[4] = C0 * C1; v01b[5] = C0 * S1;
        v01b[6] = S0;  v01b[7] = S0 * C1; v01b[8] = S0 * S1;
        v23b[0] = 1.f; v23b[1] = C3;      v23b[2] = S3;
        v23b[3] = C2;  v23b[4] = C2 * C3; v23b[5] = C2 * S3;
        v23b[6] = S2;  v23b[7] = S2 * C3; v23b[8] = S2 * S3;
    }

    float za0 = 0.f, za1 = 0.f, za2 = 0.f, za3 = 0.f;
    float zb0 = 0.f, zb1 = 0.f, zb2 = 0.f, zb3 = 0.f;
    #pragma unroll
    for (int al = 0; al < 9; al++) {
        float t0a = 0.f, t1a = 0.f, t2a = 0.f, t3a = 0.f;
        float t0b = 0.f, t1b = 0.f, t2b = 0.f, t3b = 0.f;
        #pragma unroll
        for (int be = 0; be < 9; be++) {
            float4 wv = sW[al * 9 + be];          // LDS.128 broadcast, shared by both samples
            float va = v23a[be], vb = v23b[be];
            t0a = fmaf(wv.x, va, t0a); t1a = fmaf(wv.y, va, t1a);
            t2a = fmaf(wv.z, va, t2a); t3a = fmaf(wv.w, va, t3a);
            t0b = fmaf(wv.x, vb, t0b); t1b = fmaf(wv.y, vb, t1b);
            t2b = fmaf(wv.z, vb, t2b); t3b = fmaf(wv.w, vb, t3b);
        }
        float ca = v01a[al], cb = v01b[al];
        za0 = fmaf(ca, t0a, za0); za1 = fmaf(ca, t1a, za1);
        za2 = fmaf(ca, t2a, za2); za3 = fmaf(ca, t3a, za3);
        zb0 = fmaf(cb, t0b, zb0); zb1 = fmaf(cb, t1b, zb1);
        zb2 = fmaf(cb, t2b, zb2); zb3 = fmaf(cb, t3b, zb3);
    }

    // out[b, p*4 + i] — 16B aligned float4 stores
    *reinterpret_cast<float4*>(out + tid * 784 + p * 4)         = make_float4(za0, za1, za2, za3);
    *reinterpret_cast<float4*>(out + (tid + 256) * 784 + p * 4) = make_float4(zb0, zb1, zb2, zb3);
}

extern "C" void kernel_launch(void* const* d_in, const int* in_sizes, int n_in,
                              void* d_out, int out_size) {
    const float* x      = (const float*)d_in[0];   // (512, 28, 28)
    const float* params = (const float*)d_in[1];   // (2, 4, 3)
    float* out          = (float*)d_out;           // (512, 784)

    qf_fused<<<NLOC, 256>>>(x, params, out);
}